// round 11
// baseline (speedup 1.0000x reference)
#include <cuda_runtime.h>
#include <cuda_fp16.h>
#include <cstdint>

// Problem constants
constexpr int NB = 8;     // batch
constexpr int NC = 512;   // channels
constexpr int NW = 2048;  // width (sequence)
constexpr int NQ = 64;    // C/8 (qk head dim)
constexpr int NM = 2 * NQ + NC;  // 640 fused output channels

// Scratch (device globals; allocation-free per harness rules).
__device__ __align__(16) uint16_t g_wh[(size_t)NM * NC];         // W hi [m][c]
__device__ __align__(16) uint16_t g_wl[(size_t)NM * NC];         // W lo
__device__ __align__(16) uint16_t g_xth[(size_t)NB * NW * NC];   // x^T hi [b][w][c]
__device__ __align__(16) uint16_t g_qkh[(size_t)NB * NW * 128];  // q|k hi [b][pos][ch]
__device__ __align__(16) uint16_t g_qkl[(size_t)NB * NW * 64];   // q lo   [b][pos][ch<64]
__device__ __align__(16) uint16_t g_vh[(size_t)NB * NC * NW];    // v hi [b][c][j]
__device__ __align__(16) uint16_t g_vl[(size_t)NB * NC * NW];    // v lo
__device__ __align__(16) float    g_att[(size_t)NB * NW * NW];   // energy S [b][i][j]
__device__ __align__(16) uint16_t g_ph[(size_t)NB * NW * NW];    // P hi [b][i][j]

// ---------------- helpers ----------------------------------------------------

__device__ __forceinline__ uint32_t smem_u32(const void* p) {
    uint32_t a;
    asm("{ .reg .u64 t; cvta.to.shared.u64 t, %1; cvt.u32.u64 %0, t; }"
        : "=r"(a) : "l"(p));
    return a;
}

__device__ __forceinline__ uint32_t h2(float a, float b) {
    __half2 t = __floats2half2_rn(a, b);
    return *(uint32_t*)&t;
}
__device__ __forceinline__ uint32_t l2f(float a, float b) {
    __half2 t = __floats2half2_rn(a, b);
    float2 f = __half22float2(t);
    __half2 r = __floats2half2_rn(a - f.x, b - f.y);
    return *(uint32_t*)&r;
}
__device__ __forceinline__ unsigned short h1(float a) {
    __half t = __float2half_rn(a);
    return *(unsigned short*)&t;
}
__device__ __forceinline__ unsigned short l1f(float a) {
    __half t = __float2half_rn(a);
    __half r = __float2half_rn(a - __half2float(t));
    return *(unsigned short*)&r;
}

#define LDSM_X4(R0, R1, R2, R3, A)                                            \
    asm volatile("ldmatrix.sync.aligned.m8n8.x4.shared.b16 {%0,%1,%2,%3}, [%4];" \
                 : "=r"(R0), "=r"(R1), "=r"(R2), "=r"(R3) : "r"(A))

#define MMA_F16(c, a, b)                                                      \
    asm volatile("mma.sync.aligned.m16n8k16.row.col.f32.f16.f16.f32 "         \
                 "{%0,%1,%2,%3}, {%4,%5,%6,%7}, {%8,%9}, {%0,%1,%2,%3};"      \
                 : "+f"((c)[0]), "+f"((c)[1]), "+f"((c)[2]), "+f"((c)[3])     \
                 : "r"((a)[0]), "r"((a)[1]), "r"((a)[2]), "r"((a)[3]),        \
                   "r"((b)[0]), "r"((b)[1]))

#define CP_ASYNC16(smem, gptr)                                                \
    asm volatile("cp.async.cg.shared.global [%0], [%1], 16;"                  \
                 :: "r"(smem), "l"(gptr))
#define CP_COMMIT() asm volatile("cp.async.commit_group;" ::: "memory")
#define CP_WAIT1()  asm volatile("cp.async.wait_group 1;" ::: "memory")
#define CP_WAIT0()  asm volatile("cp.async.wait_group 0;" ::: "memory")

// K=32-chunk geometry: A row [32 hi][32 lo][8] = 72 el (144 B); B row [32 hi][8] = 40 el
constexpr int SRA32 = 72;
constexpr int SRB32 = 40;
constexpr int TA32  = 128 * SRA32 * 2;   // 18432 B
constexpr int TB32  = 128 * SRB32 * 2;   // 10240 B
constexpr int ST32  = TA32 + TB32;       // 28672 B per stage
constexpr int GEMM_SMEM = 2 * ST32;      // 57344 B

// K=64 geometry (energy): A row [64 hi][64 lo][8] = 136 el; B row [64 hi][8] = 72 el
constexpr int SRA64 = 136;
constexpr int SRB64 = 72;
constexpr int TA64  = 128 * SRA64 * 2;   // 34816 B
constexpr int TB64  = 128 * SRB64 * 2;   // 18432 B
constexpr int EN_SMEM = TA64 + TB64;     // 53248 B

// ---------------- warp-tile 64x64 stage, fp16 2-product ---------------------
// acc[4][8][4]: mf (4 x m16), nf (8 x n8).  C += Ah*Bh + Al*Bh.

template <int SRA, int SRB, int LOA, int NKS>
__device__ __forceinline__ void stage64(float acc[4][8][4], uint32_t aBase,
                                        uint32_t bBase, int wm, int wn,
                                        int lane) {
#pragma unroll
    for (int ks = 0; ks < NKS; ks++) {
        const int kb = ks * 16;
        uint32_t Ah[4][4], Al[4][4], Bh[8][2];
        const int am = wm * 64 + (lane & 15);
        const int ak = kb + ((lane >> 4) << 3);
#pragma unroll
        for (int mf = 0; mf < 4; mf++) {
            uint32_t addr = aBase + ((am + mf * 16) * SRA + ak) * 2;
            LDSM_X4(Ah[mf][0], Ah[mf][1], Ah[mf][2], Ah[mf][3], addr);
            LDSM_X4(Al[mf][0], Al[mf][1], Al[mf][2], Al[mf][3], addr + LOA);
        }
        const int bn = wn * 64 + ((lane >> 4) << 3) + (lane & 7);
        const int bk = kb + (((lane >> 3) & 1) << 3);
#pragma unroll
        for (int nfp = 0; nfp < 4; nfp++) {
            uint32_t addr = bBase + ((bn + nfp * 16) * SRB + bk) * 2;
            LDSM_X4(Bh[2 * nfp][0], Bh[2 * nfp][1],
                    Bh[2 * nfp + 1][0], Bh[2 * nfp + 1][1], addr);
        }
#pragma unroll
        for (int mf = 0; mf < 4; mf++)
#pragma unroll
            for (int nf = 0; nf < 8; nf++)
                MMA_F16(acc[mf][nf], Ah[mf], Bh[nf]);
#pragma unroll
        for (int mf = 0; mf < 4; mf++)
#pragma unroll
            for (int nf = 0; nf < 8; nf++)
                MMA_F16(acc[mf][nf], Al[mf], Bh[nf]);
    }
}

// ---------------- Kernel W: split weights into fp16 planes ------------------

__global__ void __launch_bounds__(128)
wprep_kernel(const float* __restrict__ Wq, const float* __restrict__ Wk,
             const float* __restrict__ Wv) {
    const int m = blockIdx.x;
    const float* src;
    if (m < NQ)            src = Wq + (size_t)m * NC;
    else if (m < 2 * NQ)   src = Wk + (size_t)(m - NQ) * NC;
    else                   src = Wv + (size_t)(m - 2 * NQ) * NC;
    const int c4 = threadIdx.x * 4;
    float4 v = *(const float4*)(src + c4);
    size_t o = (size_t)m * NC + c4;
    *(uint2*)(g_wh + o) = make_uint2(h2(v.x, v.y), h2(v.z, v.w));
    *(uint2*)(g_wl + o) = make_uint2(l2f(v.x, v.y), l2f(v.z, v.w));
}

// ---------------- Kernel 0: transpose x -> [b][w][c] fp16 hi plane ----------

__global__ void __launch_bounds__(256)
transpose_x_kernel(const float* __restrict__ x) {
    __shared__ float s[64][65];
    const int b  = blockIdx.z;
    const int c0 = blockIdx.y * 64;
    const int w0 = blockIdx.x * 64;
    const int tid = threadIdx.x;

#pragma unroll
    for (int it = 0; it < 4; it++) {
        int c  = it * 16 + (tid >> 4);
        int w4 = (tid & 15) * 4;
        float4 v =
            *(const float4*)(x + ((size_t)b * NC + c0 + c) * NW + w0 + w4);
        s[c][w4 + 0] = v.x; s[c][w4 + 1] = v.y;
        s[c][w4 + 2] = v.z; s[c][w4 + 3] = v.w;
    }
    __syncthreads();

#pragma unroll
    for (int it = 0; it < 4; it++) {
        int w  = it * 16 + (tid >> 4);
        int c4 = (tid & 15) * 4;
        float f0 = s[c4 + 0][w], f1 = s[c4 + 1][w];
        float f2 = s[c4 + 2][w], f3 = s[c4 + 3][w];
        size_t o = ((size_t)b * NW + w0 + w) * NC + c0 + c4;
        *(uint2*)(g_xth + o) = make_uint2(h2(f0, f1), h2(f2, f3));
    }
}

// ---------------- Kernel 1: QKV GEMM (128 thr, 64x64 warp tiles) ------------

__global__ void __launch_bounds__(128, 2)
qkv_mma_kernel(const float* __restrict__ bq, const float* __restrict__ bk,
               const float* __restrict__ bv) {
    extern __shared__ uint16_t smem[];
    const int b  = blockIdx.z;
    const int m0 = blockIdx.y * 128;
    const int w0 = blockIdx.x * 128;
    const int tid  = threadIdx.x;
    const int wid  = tid >> 5;
    const int lane = tid & 31;
    const int wm = wid >> 1, wn = wid & 1;

    const uint32_t sbase = smem_u32(smem);

    // loader: 1 thread per row (tid = row), 32 cols per chunk
    const uint16_t* rAh = g_wh + (size_t)(m0 + tid) * NC;
    const uint16_t* rAl = g_wl + (size_t)(m0 + tid) * NC;
    const uint16_t* rBh = g_xth + ((size_t)b * NW + w0 + tid) * NC;
    const uint32_t aRow = tid * (SRA32 * 2);
    const uint32_t bRow = tid * (SRB32 * 2);

    float acc[4][8][4];
#pragma unroll
    for (int mf = 0; mf < 4; mf++)
#pragma unroll
        for (int nf = 0; nf < 8; nf++)
#pragma unroll
            for (int e = 0; e < 4; e++) acc[mf][nf][e] = 0.f;

    constexpr int NCH = NC / 32;   // 16

#define QKV_ISSUE(i)                                                          \
    do {                                                                      \
        const uint32_t st = sbase + ((i) & 1) * ST32;                         \
        const int kk = (i) * 32;                                              \
        _Pragma("unroll")                                                     \
        for (int q = 0; q < 4; q++) {                                         \
            CP_ASYNC16(st + aRow + q * 16,            rAh + kk + 8 * q);      \
            CP_ASYNC16(st + aRow + 64 + q * 16,       rAl + kk + 8 * q);      \
            CP_ASYNC16(st + TA32 + bRow + q * 16,     rBh + kk + 8 * q);      \
        }                                                                     \
        CP_COMMIT();                                                          \
    } while (0)

    QKV_ISSUE(0);
#pragma unroll 1
    for (int i = 0; i < NCH; i++) {
        if (i + 1 < NCH) { QKV_ISSUE(i + 1); CP_WAIT1(); } else { CP_WAIT0(); }
        __syncthreads();
        const uint32_t aBase = sbase + (i & 1) * ST32;
        stage64<SRA32, SRB32, 64, 2>(acc, aBase, aBase + TA32, wm, wn, lane);
        __syncthreads();
    }
#undef QKV_ISSUE

    // epilogue: q hi+lo (transposed), k hi (transposed), v hi+lo planes
#pragma unroll
    for (int mf = 0; mf < 4; mf++) {
#pragma unroll
        for (int half = 0; half < 2; half++) {
            const int m = m0 + wm * 64 + mf * 16 + (lane >> 2) + 8 * half;
            if (m0 == 0 && m < 128) {
                const float bias = (m < NQ) ? bq[m] : bk[m - NQ];
#pragma unroll
                for (int nf = 0; nf < 8; nf++) {
                    const int n = w0 + wn * 64 + nf * 8 + ((lane & 3) << 1);
                    float y0 = acc[mf][nf][2 * half + 0] + bias;
                    float y1 = acc[mf][nf][2 * half + 1] + bias;
                    size_t o0 = ((size_t)b * NW + n) * 128 + m;
                    size_t o1 = o0 + 128;
                    g_qkh[o0] = h1(y0);
                    g_qkh[o1] = h1(y1);
                    if (m < NQ) {
                        size_t l0 = ((size_t)b * NW + n) * 64 + m;
                        g_qkl[l0]      = l1f(y0);
                        g_qkl[l0 + 64] = l1f(y1);
                    }
                }
            } else if (m0 > 0) {
                const int c = m - 128;
                const float bias = bv[c];
#pragma unroll
                for (int nf = 0; nf < 8; nf++) {
                    const int n = w0 + wn * 64 + nf * 8 + ((lane & 3) << 1);
                    float y0 = acc[mf][nf][2 * half + 0] + bias;
                    float y1 = acc[mf][nf][2 * half + 1] + bias;
                    size_t o = ((size_t)b * NC + c) * NW + n;
                    *(uint32_t*)(g_vh + o) = h2(y0, y1);
                    *(uint32_t*)(g_vl + o) = l2f(y0, y1);
                }
            }
        }
    }
}

// ---------------- Kernel 2: energy (128 thr, 64x64 warp tiles, K=64) --------

__global__ void __launch_bounds__(128, 2)
energy_mma_kernel() {
    extern __shared__ uint16_t smem[];
    const int b  = blockIdx.z;
    const int i0 = blockIdx.y * 128;
    const int j0 = blockIdx.x * 128;
    const int tid  = threadIdx.x;
    const int lane = tid & 31;
    const int wid  = tid >> 5;
    const int wm = wid >> 1, wn = wid & 1;

    const uint32_t sbase = smem_u32(smem);
    uint16_t* sA = smem;
    uint16_t* sB = smem + TA64 / 2;

    {
        const int row = tid;
        const uint16_t* qh = g_qkh + ((size_t)b * NW + i0 + row) * 128;
        const uint16_t* ql = g_qkl + ((size_t)b * NW + i0 + row) * 64;
        const uint16_t* kh = g_qkh + ((size_t)b * NW + j0 + row) * 128 + 64;
#pragma unroll
        for (int q = 0; q < 8; q++) {
            *(uint4*)(sA + row * SRA64 + 8 * q)      = *(const uint4*)(qh + 8 * q);
            *(uint4*)(sA + row * SRA64 + 64 + 8 * q) = *(const uint4*)(ql + 8 * q);
            *(uint4*)(sB + row * SRB64 + 8 * q)      = *(const uint4*)(kh + 8 * q);
        }
    }
    __syncthreads();

    float acc[4][8][4];
#pragma unroll
    for (int mf = 0; mf < 4; mf++)
#pragma unroll
        for (int nf = 0; nf < 8; nf++)
#pragma unroll
            for (int e = 0; e < 4; e++) acc[mf][nf][e] = 0.f;

    stage64<SRA64, SRB64, 128, 4>(acc, sbase, sbase + TA64, wm, wn, lane);

#pragma unroll
    for (int mf = 0; mf < 4; mf++) {
        const int m = i0 + wm * 64 + mf * 16 + (lane >> 2);
#pragma unroll
        for (int nf = 0; nf < 8; nf++) {
            const int n = j0 + wn * 64 + nf * 8 + ((lane & 3) << 1);
            size_t o0 = ((size_t)b * NW + m) * NW + n;
            *(float2*)(g_att + o0) = make_float2(acc[mf][nf][0], acc[mf][nf][1]);
            size_t o1 = o0 + (size_t)8 * NW;
            *(float2*)(g_att + o1) = make_float2(acc[mf][nf][2], acc[mf][nf][3]);
        }
    }
}

// ---------------- Kernel 3: row softmax, fp32 in, fp16 hi plane out ---------

__global__ void __launch_bounds__(256)
softmax_kernel() {
    __shared__ float red[8];
    const size_t row = blockIdx.x;
    const float* p = g_att + row * NW;
    const int tid = threadIdx.x;

    float4 v0 = *(const float4*)(p + tid * 8);
    float4 v1 = *(const float4*)(p + tid * 8 + 4);
    float e[8] = {v0.x, v0.y, v0.z, v0.w, v1.x, v1.y, v1.z, v1.w};

    float m = e[0];
#pragma unroll
    for (int i = 1; i < 8; i++) m = fmaxf(m, e[i]);
#pragma unroll
    for (int o = 16; o; o >>= 1) m = fmaxf(m, __shfl_xor_sync(0xffffffffu, m, o));
    if ((tid & 31) == 0) red[tid >> 5] = m;
    __syncthreads();
    m = red[0];
#pragma unroll
    for (int i = 1; i < 8; i++) m = fmaxf(m, red[i]);

    float s = 0.f;
#pragma unroll
    for (int i = 0; i < 8; i++) { e[i] = __expf(e[i] - m); s += e[i]; }
#pragma unroll
    for (int o = 16; o; o >>= 1) s += __shfl_xor_sync(0xffffffffu, s, o);
    __syncthreads();
    if ((tid & 31) == 0) red[tid >> 5] = s;
    __syncthreads();
    s = 0.f;
#pragma unroll
    for (int i = 0; i < 8; i++) s += red[i];

    float inv = 1.0f / s;
#pragma unroll
    for (int i = 0; i < 8; i++) e[i] *= inv;

    *(uint4*)(g_ph + row * NW + tid * 8) =
        make_uint4(h2(e[0], e[1]), h2(e[2], e[3]),
                   h2(e[4], e[5]), h2(e[6], e[7]));
}

// ---------------- Kernel 4: out GEMM (128 thr, 64x64 warp tiles) ------------
// out[c,i] = gamma * sum_j v[c,j] P[i,j] + x[c,i].  A = v hi/lo, B = P hi.

__global__ void __launch_bounds__(128, 2)
out_mma_kernel(const float* __restrict__ x, const float* __restrict__ gamma,
               float* __restrict__ out) {
    extern __shared__ uint16_t smem[];
    const int b  = blockIdx.z;
    const int c0 = blockIdx.x * 128;
    const int i0 = blockIdx.y * 128;
    const int tid  = threadIdx.x;
    const int wid  = tid >> 5;
    const int lane = tid & 31;
    const int wm = wid >> 1, wn = wid & 1;

    const uint32_t sbase = smem_u32(smem);

    const uint16_t* rAh = g_vh + ((size_t)b * NC + c0 + tid) * NW;
    const uint16_t* rAl = g_vl + ((size_t)b * NC + c0 + tid) * NW;
    const uint16_t* rBh = g_ph + ((size_t)b * NW + i0 + tid) * NW;
    const uint32_t aRow = tid * (SRA32 * 2);
    const uint32_t bRow = tid * (SRB32 * 2);

    float acc[4][8][4];
#pragma unroll
    for (int mf = 0; mf < 4; mf++)
#pragma unroll
        for (int nf = 0; nf < 8; nf++)
#pragma unroll
            for (int e = 0; e < 4; e++) acc[mf][nf][e] = 0.f;

    constexpr int NCH = NW / 32;   // 64

#define OUT_ISSUE(i)                                                          \
    do {                                                                      \
        const uint32_t st = sbase + ((i) & 1) * ST32;                         \
        const int kk = (i) * 32;                                              \
        _Pragma("unroll")                                                     \
        for (int q = 0; q < 4; q++) {                                         \
            CP_ASYNC16(st + aRow + q * 16,            rAh + kk + 8 * q);      \
            CP_ASYNC16(st + aRow + 64 + q * 16,       rAl + kk + 8 * q);      \
            CP_ASYNC16(st + TA32 + bRow + q * 16,     rBh + kk + 8 * q);      \
        }                                                                     \
        CP_COMMIT();                                                          \
    } while (0)

    OUT_ISSUE(0);
#pragma unroll 1
    for (int i = 0; i < NCH; i++) {
        if (i + 1 < NCH) { OUT_ISSUE(i + 1); CP_WAIT1(); } else { CP_WAIT0(); }
        __syncthreads();
        const uint32_t aBase = sbase + (i & 1) * ST32;
        stage64<SRA32, SRB32, 64, 2>(acc, aBase, aBase + TA32, wm, wn, lane);
        __syncthreads();
    }
#undef OUT_ISSUE

    const float gam = gamma[0];
#pragma unroll
    for (int mf = 0; mf < 4; mf++) {
        const int m = c0 + wm * 64 + mf * 16 + (lane >> 2);
#pragma unroll
        for (int nf = 0; nf < 8; nf++) {
            const int n = i0 + wn * 64 + nf * 8 + ((lane & 3) << 1);
            size_t o0 = ((size_t)b * NC + m) * NW + n;
            float2 xv0 = *(const float2*)(x + o0);
            *(float2*)(out + o0) = make_float2(fmaf(gam, acc[mf][nf][0], xv0.x),
                                               fmaf(gam, acc[mf][nf][1], xv0.y));
            size_t o1 = o0 + (size_t)8 * NW;
            float2 xv1 = *(const float2*)(x + o1);
            *(float2*)(out + o1) = make_float2(fmaf(gam, acc[mf][nf][2], xv1.x),
                                               fmaf(gam, acc[mf][nf][3], xv1.y));
        }
    }
}

// ---------------- launch ----------------------------------------------------

extern "C" void kernel_launch(void* const* d_in, const int* in_sizes, int n_in,
                              void* d_out, int out_size) {
    const float* x     = (const float*)d_in[0];
    const float* Wq    = (const float*)d_in[1];
    const float* bq    = (const float*)d_in[2];
    const float* Wk    = (const float*)d_in[3];
    const float* bk    = (const float*)d_in[4];
    const float* Wv    = (const float*)d_in[5];
    const float* bv    = (const float*)d_in[6];
    const float* gamma = (const float*)d_in[7];
    float* out = (float*)d_out;

    cudaFuncSetAttribute(qkv_mma_kernel,
                         cudaFuncAttributeMaxDynamicSharedMemorySize, GEMM_SMEM);
    cudaFuncSetAttribute(energy_mma_kernel,
                         cudaFuncAttributeMaxDynamicSharedMemorySize, EN_SMEM);
    cudaFuncSetAttribute(out_mma_kernel,
                         cudaFuncAttributeMaxDynamicSharedMemorySize, GEMM_SMEM);

    wprep_kernel<<<NM, 128>>>(Wq, Wk, Wv);
    transpose_x_kernel<<<dim3(NW / 64, NC / 64, NB), 256>>>(x);
    qkv_mma_kernel<<<dim3(NW / 128, 5, NB), 128, GEMM_SMEM>>>(bq, bk, bv);
    energy_mma_kernel<<<dim3(NW / 128, NW / 128, NB), 128, EN_SMEM>>>();
    softmax_kernel<<<NB * NW, 256>>>();
    out_mma_kernel<<<dim3(NC / 128, NW / 128, NB), 128, GEMM_SMEM>>>(x, gamma, out);
}

// round 12
// speedup vs baseline: 1.3463x; 1.3463x over previous
#include <cuda_runtime.h>
#include <cuda_fp16.h>
#include <cstdint>

// Problem constants
constexpr int NB = 8;     // batch
constexpr int NC = 512;   // channels
constexpr int NW = 2048;  // width (sequence)
constexpr int NQ = 64;    // C/8 (qk head dim)
constexpr int NM = 2 * NQ + NC;  // 640 fused output channels

// Scratch (device globals; allocation-free per harness rules).
// Pure fp16 single-plane pipeline.
__device__ __align__(16) uint16_t g_wh[(size_t)NM * NC];         // W [m][c]
__device__ __align__(16) uint16_t g_xth[(size_t)NB * NW * NC];   // x^T [b][w][c]
__device__ __align__(16) uint16_t g_qkh[(size_t)NB * NW * 128];  // q|k [b][pos][ch]
__device__ __align__(16) uint16_t g_vh[(size_t)NB * NC * NW];    // v [b][c][j]
__device__ __align__(16) float    g_att[(size_t)NB * NW * NW];   // energy S [b][i][j]
__device__ __align__(16) uint16_t g_ph[(size_t)NB * NW * NW];    // P [b][i][j]

// ---------------- helpers ----------------------------------------------------

__device__ __forceinline__ uint32_t smem_u32(const void* p) {
    uint32_t a;
    asm("{ .reg .u64 t; cvta.to.shared.u64 t, %1; cvt.u32.u64 %0, t; }"
        : "=r"(a) : "l"(p));
    return a;
}

__device__ __forceinline__ uint32_t h2(float a, float b) {
    __half2 t = __floats2half2_rn(a, b);
    return *(uint32_t*)&t;
}
__device__ __forceinline__ unsigned short h1(float a) {
    __half t = __float2half_rn(a);
    return *(unsigned short*)&t;
}

#define LDSM_X4(R0, R1, R2, R3, A)                                            \
    asm volatile("ldmatrix.sync.aligned.m8n8.x4.shared.b16 {%0,%1,%2,%3}, [%4];" \
                 : "=r"(R0), "=r"(R1), "=r"(R2), "=r"(R3) : "r"(A))

#define MMA_F16(c, a, b)                                                      \
    asm volatile("mma.sync.aligned.m16n8k16.row.col.f32.f16.f16.f32 "         \
                 "{%0,%1,%2,%3}, {%4,%5,%6,%7}, {%8,%9}, {%0,%1,%2,%3};"      \
                 : "+f"((c)[0]), "+f"((c)[1]), "+f"((c)[2]), "+f"((c)[3])     \
                 : "r"((a)[0]), "r"((a)[1]), "r"((a)[2]), "r"((a)[3]),        \
                   "r"((b)[0]), "r"((b)[1]))

// K=32-chunk geometry: row = [32][8 pad] fp16 -> stride 40 el (80 B, 5x16B:
// conflict-free for LDSM, proven by R10's SRB32=40)
constexpr int SR32 = 40;
constexpr int T32  = 128 * SR32 * 2;     // 10240 B per operand tile
constexpr int ST32 = 2 * T32;            // 20480 B per stage (A + B)
constexpr int GEMM_SMEM = 2 * ST32;      // 40960 B double-buffered

// K=64 geometry (energy): row = [64][8 pad] -> stride 72 el (144 B, 9x16B)
constexpr int SR64 = 72;
constexpr int T64  = 128 * SR64 * 2;     // 18432 B
constexpr int EN_SMEM = 2 * T64;         // 36864 B

// ---------------- warp-tile 64x32 stage, fp16 single product ----------------
// acc[4][4][4]: mf (4 x m16), nf (4 x n8).  C += A*B.

template <int SRA, int SRB, int NKS>
__device__ __forceinline__ void stage1(float acc[4][4][4], uint32_t aBase,
                                       uint32_t bBase, int wm, int wn,
                                       int lane) {
#pragma unroll
    for (int ks = 0; ks < NKS; ks++) {
        const int kb = ks * 16;
        uint32_t Ah[4][4], Bh[4][2];
        const int am = wm * 64 + (lane & 15);
        const int ak = kb + ((lane >> 4) << 3);
#pragma unroll
        for (int mf = 0; mf < 4; mf++) {
            uint32_t addr = aBase + ((am + mf * 16) * SRA + ak) * 2;
            LDSM_X4(Ah[mf][0], Ah[mf][1], Ah[mf][2], Ah[mf][3], addr);
        }
        const int bn = wn * 32 + ((lane >> 4) << 3) + (lane & 7);
        const int bk = kb + (((lane >> 3) & 1) << 3);
#pragma unroll
        for (int nfp = 0; nfp < 2; nfp++) {
            uint32_t addr = bBase + ((bn + nfp * 16) * SRB + bk) * 2;
            LDSM_X4(Bh[2 * nfp][0], Bh[2 * nfp][1],
                    Bh[2 * nfp + 1][0], Bh[2 * nfp + 1][1], addr);
        }
#pragma unroll
        for (int mf = 0; mf < 4; mf++)
#pragma unroll
            for (int nf = 0; nf < 4; nf++)
                MMA_F16(acc[mf][nf], Ah[mf], Bh[nf]);
    }
}

// ---------------- Kernel W: convert weights to fp16 -------------------------

__global__ void __launch_bounds__(128)
wprep_kernel(const float* __restrict__ Wq, const float* __restrict__ Wk,
             const float* __restrict__ Wv) {
    const int m = blockIdx.x;
    const float* src;
    if (m < NQ)            src = Wq + (size_t)m * NC;
    else if (m < 2 * NQ)   src = Wk + (size_t)(m - NQ) * NC;
    else                   src = Wv + (size_t)(m - 2 * NQ) * NC;
    const int c4 = threadIdx.x * 4;
    float4 v = *(const float4*)(src + c4);
    *(uint2*)(g_wh + (size_t)m * NC + c4) =
        make_uint2(h2(v.x, v.y), h2(v.z, v.w));
}

// ---------------- Kernel 0: transpose x -> [b][w][c] fp16 -------------------

__global__ void __launch_bounds__(256)
transpose_x_kernel(const float* __restrict__ x) {
    __shared__ float s[64][65];
    const int b  = blockIdx.z;
    const int c0 = blockIdx.y * 64;
    const int w0 = blockIdx.x * 64;
    const int tid = threadIdx.x;

#pragma unroll
    for (int it = 0; it < 4; it++) {
        int c  = it * 16 + (tid >> 4);
        int w4 = (tid & 15) * 4;
        float4 v =
            *(const float4*)(x + ((size_t)b * NC + c0 + c) * NW + w0 + w4);
        s[c][w4 + 0] = v.x; s[c][w4 + 1] = v.y;
        s[c][w4 + 2] = v.z; s[c][w4 + 3] = v.w;
    }
    __syncthreads();

#pragma unroll
    for (int it = 0; it < 4; it++) {
        int w  = it * 16 + (tid >> 4);
        int c4 = (tid & 15) * 4;
        float f0 = s[c4 + 0][w], f1 = s[c4 + 1][w];
        float f2 = s[c4 + 2][w], f3 = s[c4 + 3][w];
        size_t o = ((size_t)b * NW + w0 + w) * NC + c0 + c4;
        *(uint2*)(g_xth + o) = make_uint2(h2(f0, f1), h2(f2, f3));
    }
}

// ---------------- Kernel 1: QKV GEMM (fp16 1-product) -----------------------
// Y[m,w] = sum_c W[m,c] x[c,w] + bias.

__global__ void __launch_bounds__(256, 1)
qkv_mma_kernel(const float* __restrict__ bq, const float* __restrict__ bk,
               const float* __restrict__ bv) {
    extern __shared__ uint16_t smem[];
    const int b  = blockIdx.z;
    const int m0 = blockIdx.y * 128;
    const int w0 = blockIdx.x * 128;
    const int tid  = threadIdx.x;
    const int wid  = tid >> 5;
    const int lane = tid & 31;
    const int wm = wid >> 2, wn = wid & 3;

    const uint32_t sbase = smem_u32(smem);

    const int row = tid >> 1;
    const int c16 = (tid & 1) * 16;
    const uint16_t* rA = g_wh + (size_t)(m0 + row) * NC + c16;
    const uint16_t* rB = g_xth + ((size_t)b * NW + w0 + row) * NC + c16;

    float acc[4][4][4];
#pragma unroll
    for (int mf = 0; mf < 4; mf++)
#pragma unroll
        for (int nf = 0; nf < 4; nf++)
#pragma unroll
            for (int e = 0; e < 4; e++) acc[mf][nf][e] = 0.f;

    uint4 pa[2], pb[2];
#pragma unroll
    for (int q = 0; q < 2; q++) {
        pa[q] = *(const uint4*)(rA + 8 * q);
        pb[q] = *(const uint4*)(rB + 8 * q);
    }

    constexpr int NCH = NC / 32;   // 16
#pragma unroll 1
    for (int chunk = 0; chunk < NCH; chunk++) {
        const int p = chunk & 1;
        uint16_t* sA = smem + p * (ST32 / 2);
        uint16_t* sB = sA + T32 / 2;
#pragma unroll
        for (int q = 0; q < 2; q++) {
            *(uint4*)(sA + row * SR32 + c16 + 8 * q) = pa[q];
            *(uint4*)(sB + row * SR32 + c16 + 8 * q) = pb[q];
        }
        __syncthreads();

        if (chunk < NCH - 1) {
            const int kk = (chunk + 1) * 32;
#pragma unroll
            for (int q = 0; q < 2; q++) {
                pa[q] = *(const uint4*)(rA + kk + 8 * q);
                pb[q] = *(const uint4*)(rB + kk + 8 * q);
            }
        }

        const uint32_t aBase = sbase + p * ST32;
        stage1<SR32, SR32, 2>(acc, aBase, aBase + T32, wm, wn, lane);
    }

    // epilogue: q/k transposed into g_qkh, v natural into g_vh
#pragma unroll
    for (int mf = 0; mf < 4; mf++) {
#pragma unroll
        for (int half = 0; half < 2; half++) {
            const int m = m0 + wm * 64 + mf * 16 + (lane >> 2) + 8 * half;
            if (m0 == 0 && m < 128) {
                const float bias = (m < NQ) ? bq[m] : bk[m - NQ];
#pragma unroll
                for (int nf = 0; nf < 4; nf++) {
                    const int n = w0 + wn * 32 + nf * 8 + ((lane & 3) << 1);
                    float y0 = acc[mf][nf][2 * half + 0] + bias;
                    float y1 = acc[mf][nf][2 * half + 1] + bias;
                    size_t o0 = ((size_t)b * NW + n) * 128 + m;
                    g_qkh[o0]       = h1(y0);
                    g_qkh[o0 + 128] = h1(y1);
                }
            } else if (m0 > 0) {
                const int c = m - 128;
                const float bias = bv[c];
#pragma unroll
                for (int nf = 0; nf < 4; nf++) {
                    const int n = w0 + wn * 32 + nf * 8 + ((lane & 3) << 1);
                    float y0 = acc[mf][nf][2 * half + 0] + bias;
                    float y1 = acc[mf][nf][2 * half + 1] + bias;
                    *(uint32_t*)(g_vh + ((size_t)b * NC + c) * NW + n) = h2(y0, y1);
                }
            }
        }
    }
}

// ---------------- Kernel 2: energy (fp16 1-product, K=64 single shot) -------

__global__ void __launch_bounds__(256, 1)
energy_mma_kernel() {
    extern __shared__ uint16_t smem[];
    const int b  = blockIdx.z;
    const int i0 = blockIdx.y * 128;
    const int j0 = blockIdx.x * 128;
    const int tid  = threadIdx.x;
    const int lane = tid & 31;
    const int wid  = tid >> 5;
    const int wm = wid >> 2, wn = wid & 3;

    const uint32_t sbase = smem_u32(smem);
    uint16_t* sA = smem;
    uint16_t* sB = smem + T64 / 2;

    const int row = tid >> 1;
    const int h32 = (tid & 1) * 32;
    {
        const uint16_t* qh = g_qkh + ((size_t)b * NW + i0 + row) * 128 + h32;
        const uint16_t* kh = g_qkh + ((size_t)b * NW + j0 + row) * 128 + 64 + h32;
#pragma unroll
        for (int q = 0; q < 4; q++) {
            *(uint4*)(sA + row * SR64 + h32 + 8 * q) = *(const uint4*)(qh + 8 * q);
            *(uint4*)(sB + row * SR64 + h32 + 8 * q) = *(const uint4*)(kh + 8 * q);
        }
    }
    __syncthreads();

    float acc[4][4][4];
#pragma unroll
    for (int mf = 0; mf < 4; mf++)
#pragma unroll
        for (int nf = 0; nf < 4; nf++)
#pragma unroll
            for (int e = 0; e < 4; e++) acc[mf][nf][e] = 0.f;

    stage1<SR64, SR64, 4>(acc, sbase, sbase + T64, wm, wn, lane);

#pragma unroll
    for (int mf = 0; mf < 4; mf++) {
        const int m = i0 + wm * 64 + mf * 16 + (lane >> 2);
#pragma unroll
        for (int nf = 0; nf < 4; nf++) {
            const int n = j0 + wn * 32 + nf * 8 + ((lane & 3) << 1);
            size_t o0 = ((size_t)b * NW + m) * NW + n;
            *(float2*)(g_att + o0) = make_float2(acc[mf][nf][0], acc[mf][nf][1]);
            size_t o1 = o0 + (size_t)8 * NW;
            *(float2*)(g_att + o1) = make_float2(acc[mf][nf][2], acc[mf][nf][3]);
        }
    }
}

// ---------------- Kernel 3: row softmax, fp32 in, fp16 out ------------------

__global__ void __launch_bounds__(256)
softmax_kernel() {
    __shared__ float red[8];
    const size_t row = blockIdx.x;
    const float* p = g_att + row * NW;
    const int tid = threadIdx.x;

    float4 v0 = *(const float4*)(p + tid * 8);
    float4 v1 = *(const float4*)(p + tid * 8 + 4);
    float e[8] = {v0.x, v0.y, v0.z, v0.w, v1.x, v1.y, v1.z, v1.w};

    float m = e[0];
#pragma unroll
    for (int i = 1; i < 8; i++) m = fmaxf(m, e[i]);
#pragma unroll
    for (int o = 16; o; o >>= 1) m = fmaxf(m, __shfl_xor_sync(0xffffffffu, m, o));
    if ((tid & 31) == 0) red[tid >> 5] = m;
    __syncthreads();
    m = red[0];
#pragma unroll
    for (int i = 1; i < 8; i++) m = fmaxf(m, red[i]);

    float s = 0.f;
#pragma unroll
    for (int i = 0; i < 8; i++) { e[i] = __expf(e[i] - m); s += e[i]; }
#pragma unroll
    for (int o = 16; o; o >>= 1) s += __shfl_xor_sync(0xffffffffu, s, o);
    __syncthreads();
    if ((tid & 31) == 0) red[tid >> 5] = s;
    __syncthreads();
    s = 0.f;
#pragma unroll
    for (int i = 0; i < 8; i++) s += red[i];

    float inv = 1.0f / s;
#pragma unroll
    for (int i = 0; i < 8; i++) e[i] *= inv;

    *(uint4*)(g_ph + row * NW + tid * 8) =
        make_uint4(h2(e[0], e[1]), h2(e[2], e[3]),
                   h2(e[4], e[5]), h2(e[6], e[7]));
}

// ---------------- Kernel 4: out GEMM (fp16 1-product) -----------------------
// out[c,i] = gamma * sum_j v[c,j] P[i,j] + x[c,i].

__global__ void __launch_bounds__(256, 1)
out_mma_kernel(const float* __restrict__ x, const float* __restrict__ gamma,
               float* __restrict__ out) {
    extern __shared__ uint16_t smem[];
    const int b  = blockIdx.z;
    const int c0 = blockIdx.x * 128;
    const int i0 = blockIdx.y * 128;
    const int tid  = threadIdx.x;
    const int wid  = tid >> 5;
    const int lane = tid & 31;
    const int wm = wid >> 2, wn = wid & 3;

    const uint32_t sbase = smem_u32(smem);

    const int row = tid >> 1;
    const int c16 = (tid & 1) * 16;
    const uint16_t* rA = g_vh + ((size_t)b * NC + c0 + row) * NW + c16;
    const uint16_t* rB = g_ph + ((size_t)b * NW + i0 + row) * NW + c16;

    float acc[4][4][4];
#pragma unroll
    for (int mf = 0; mf < 4; mf++)
#pragma unroll
        for (int nf = 0; nf < 4; nf++)
#pragma unroll
            for (int e = 0; e < 4; e++) acc[mf][nf][e] = 0.f;

    uint4 pa[2], pb[2];
#pragma unroll
    for (int q = 0; q < 2; q++) {
        pa[q] = *(const uint4*)(rA + 8 * q);
        pb[q] = *(const uint4*)(rB + 8 * q);
    }

    constexpr int NCH = NW / 32;   // 64
#pragma unroll 1
    for (int chunk = 0; chunk < NCH; chunk++) {
        const int p = chunk & 1;
        uint16_t* sA = smem + p * (ST32 / 2);
        uint16_t* sB = sA + T32 / 2;
#pragma unroll
        for (int q = 0; q < 2; q++) {
            *(uint4*)(sA + row * SR32 + c16 + 8 * q) = pa[q];
            *(uint4*)(sB + row * SR32 + c16 + 8 * q) = pb[q];
        }
        __syncthreads();

        if (chunk < NCH - 1) {
            const int kk = (chunk + 1) * 32;
#pragma unroll
            for (int q = 0; q < 2; q++) {
                pa[q] = *(const uint4*)(rA + kk + 8 * q);
                pb[q] = *(const uint4*)(rB + kk + 8 * q);
            }
        }

        const uint32_t aBase = sbase + p * ST32;
        stage1<SR32, SR32, 2>(acc, aBase, aBase + T32, wm, wn, lane);
    }

    const float gam = gamma[0];
#pragma unroll
    for (int mf = 0; mf < 4; mf++) {
        const int m = c0 + wm * 64 + mf * 16 + (lane >> 2);
#pragma unroll
        for (int nf = 0; nf < 4; nf++) {
            const int n = i0 + wn * 32 + nf * 8 + ((lane & 3) << 1);
            size_t o0 = ((size_t)b * NC + m) * NW + n;
            float2 xv0 = *(const float2*)(x + o0);
            *(float2*)(out + o0) = make_float2(fmaf(gam, acc[mf][nf][0], xv0.x),
                                               fmaf(gam, acc[mf][nf][1], xv0.y));
            size_t o1 = o0 + (size_t)8 * NW;
            float2 xv1 = *(const float2*)(x + o1);
            *(float2*)(out + o1) = make_float2(fmaf(gam, acc[mf][nf][2], xv1.x),
                                               fmaf(gam, acc[mf][nf][3], xv1.y));
        }
    }
}

// ---------------- launch ----------------------------------------------------

extern "C" void kernel_launch(void* const* d_in, const int* in_sizes, int n_in,
                              void* d_out, int out_size) {
    const float* x     = (const float*)d_in[0];
    const float* Wq    = (const float*)d_in[1];
    const float* bq    = (const float*)d_in[2];
    const float* Wk    = (const float*)d_in[3];
    const float* bk    = (const float*)d_in[4];
    const float* Wv    = (const float*)d_in[5];
    const float* bv    = (const float*)d_in[6];
    const float* gamma = (const float*)d_in[7];
    float* out = (float*)d_out;

    cudaFuncSetAttribute(qkv_mma_kernel,
                         cudaFuncAttributeMaxDynamicSharedMemorySize, GEMM_SMEM);
    cudaFuncSetAttribute(energy_mma_kernel,
                         cudaFuncAttributeMaxDynamicSharedMemorySize, EN_SMEM);
    cudaFuncSetAttribute(out_mma_kernel,
                         cudaFuncAttributeMaxDynamicSharedMemorySize, GEMM_SMEM);

    wprep_kernel<<<NM, 128>>>(Wq, Wk, Wv);
    transpose_x_kernel<<<dim3(NW / 64, NC / 64, NB), 256>>>(x);
    qkv_mma_kernel<<<dim3(NW / 128, 5, NB), 256, GEMM_SMEM>>>(bq, bk, bv);
    energy_mma_kernel<<<dim3(NW / 128, NW / 128, NB), 256, EN_SMEM>>>();
    softmax_kernel<<<NB * NW, 256>>>();
    out_mma_kernel<<<dim3(NC / 128, NW / 128, NB), 256, GEMM_SMEM>>>(x, gamma, out);
}

// round 13
// speedup vs baseline: 1.3532x; 1.0051x over previous
#include <cuda_runtime.h>
#include <cuda_fp16.h>
#include <cstdint>

// Problem constants
constexpr int NB = 8;     // batch
constexpr int NC = 512;   // channels
constexpr int NW = 2048;  // width (sequence)
constexpr int NQ = 64;    // C/8 (qk head dim)
constexpr int NM = 2 * NQ + NC;  // 640 fused output channels

// Scratch (device globals; allocation-free per harness rules).
__device__ __align__(16) uint16_t g_wh[(size_t)NM * NC];         // W [m][c]
__device__ __align__(16) uint16_t g_xth[(size_t)NB * NW * NC];   // x^T [b][w][c]
__device__ __align__(16) uint16_t g_qkh[(size_t)NB * NW * 128];  // q|k [b][pos][ch]
__device__ __align__(16) uint16_t g_vh[(size_t)NB * NC * NW];    // v [b][c][j]
__device__ __align__(16) uint16_t g_ph[(size_t)NB * NW * NW];    // P unnorm [b][i][j]
__device__ __align__(16) float    g_srow[(size_t)NB * NW];       // softmax row sums

// ---------------- helpers ----------------------------------------------------

__device__ __forceinline__ uint32_t smem_u32(const void* p) {
    uint32_t a;
    asm("{ .reg .u64 t; cvta.to.shared.u64 t, %1; cvt.u32.u64 %0, t; }"
        : "=r"(a) : "l"(p));
    return a;
}

__device__ __forceinline__ uint32_t h2(float a, float b) {
    __half2 t = __floats2half2_rn(a, b);
    return *(uint32_t*)&t;
}
__device__ __forceinline__ unsigned short h1(float a) {
    __half t = __float2half_rn(a);
    return *(unsigned short*)&t;
}

#define LDSM_X4(R0, R1, R2, R3, A)                                            \
    asm volatile("ldmatrix.sync.aligned.m8n8.x4.shared.b16 {%0,%1,%2,%3}, [%4];" \
                 : "=r"(R0), "=r"(R1), "=r"(R2), "=r"(R3) : "r"(A))

#define MMA_F16(c, a, b)                                                      \
    asm volatile("mma.sync.aligned.m16n8k16.row.col.f32.f16.f16.f32 "         \
                 "{%0,%1,%2,%3}, {%4,%5,%6,%7}, {%8,%9}, {%0,%1,%2,%3};"      \
                 : "+f"((c)[0]), "+f"((c)[1]), "+f"((c)[2]), "+f"((c)[3])     \
                 : "r"((a)[0]), "r"((a)[1]), "r"((a)[2]), "r"((a)[3]),        \
                   "r"((b)[0]), "r"((b)[1]))

// K=32-chunk geometry: row = [32][8 pad] fp16 -> stride 40 el (80 B)
constexpr int SR32 = 40;
constexpr int T32  = 128 * SR32 * 2;     // 10240 B per operand tile
constexpr int ST32 = 2 * T32;            // 20480 B per stage
constexpr int GEMM_SMEM = 2 * ST32;      // 40960 B

// K=64 geometry: row = [64][8 pad] -> stride 72 el (144 B)
constexpr int SR64 = 72;
constexpr int T64  = 128 * SR64 * 2;     // 18432 B

// pmax smem layout (byte offsets; smem declared as uint16_t*)
constexpr int PM_OFF_Q   = 0;                    // sQ [128][72]
constexpr int PM_OFF_K   = T64;                  // sK double buffer 2x18432
constexpr int PM_OFF_P   = PM_OFF_K + 2 * T64;   // sP [128][136] = 34816
constexpr int SRP        = 136;
constexpr int PM_OFF_RED = PM_OFF_P + 128 * SRP * 2;  // float [4][128]
constexpr int PM_OFF_M   = PM_OFF_RED + 4 * 128 * 4;  // float [128]
constexpr int PM_OFF_S   = PM_OFF_M + 128 * 4;        // float [128]
constexpr int PM_SMEM    = PM_OFF_S + 128 * 4;        // 93184 B

// ---------------- warp-tile 64x32 stage, fp16 single product ----------------

template <int SRA, int SRB, int NKS>
__device__ __forceinline__ void stage1(float acc[4][4][4], uint32_t aBase,
                                       uint32_t bBase, int wm, int wn,
                                       int lane) {
#pragma unroll
    for (int ks = 0; ks < NKS; ks++) {
        const int kb = ks * 16;
        uint32_t Ah[4][4], Bh[4][2];
        const int am = wm * 64 + (lane & 15);
        const int ak = kb + ((lane >> 4) << 3);
#pragma unroll
        for (int mf = 0; mf < 4; mf++) {
            uint32_t addr = aBase + ((am + mf * 16) * SRA + ak) * 2;
            LDSM_X4(Ah[mf][0], Ah[mf][1], Ah[mf][2], Ah[mf][3], addr);
        }
        const int bn = wn * 32 + ((lane >> 4) << 3) + (lane & 7);
        const int bk = kb + (((lane >> 3) & 1) << 3);
#pragma unroll
        for (int nfp = 0; nfp < 2; nfp++) {
            uint32_t addr = bBase + ((bn + nfp * 16) * SRB + bk) * 2;
            LDSM_X4(Bh[2 * nfp][0], Bh[2 * nfp][1],
                    Bh[2 * nfp + 1][0], Bh[2 * nfp + 1][1], addr);
        }
#pragma unroll
        for (int mf = 0; mf < 4; mf++)
#pragma unroll
            for (int nf = 0; nf < 4; nf++)
                MMA_F16(acc[mf][nf], Ah[mf], Bh[nf]);
    }
}

// ---------------- Kernel W: convert weights to fp16 -------------------------

__global__ void __launch_bounds__(128)
wprep_kernel(const float* __restrict__ Wq, const float* __restrict__ Wk,
             const float* __restrict__ Wv) {
    const int m = blockIdx.x;
    const float* src;
    if (m < NQ)            src = Wq + (size_t)m * NC;
    else if (m < 2 * NQ)   src = Wk + (size_t)(m - NQ) * NC;
    else                   src = Wv + (size_t)(m - 2 * NQ) * NC;
    const int c4 = threadIdx.x * 4;
    float4 v = *(const float4*)(src + c4);
    *(uint2*)(g_wh + (size_t)m * NC + c4) =
        make_uint2(h2(v.x, v.y), h2(v.z, v.w));
}

// ---------------- Kernel 0: transpose x -> [b][w][c] fp16 -------------------

__global__ void __launch_bounds__(256)
transpose_x_kernel(const float* __restrict__ x) {
    __shared__ float s[64][65];
    const int b  = blockIdx.z;
    const int c0 = blockIdx.y * 64;
    const int w0 = blockIdx.x * 64;
    const int tid = threadIdx.x;

#pragma unroll
    for (int it = 0; it < 4; it++) {
        int c  = it * 16 + (tid >> 4);
        int w4 = (tid & 15) * 4;
        float4 v =
            *(const float4*)(x + ((size_t)b * NC + c0 + c) * NW + w0 + w4);
        s[c][w4 + 0] = v.x; s[c][w4 + 1] = v.y;
        s[c][w4 + 2] = v.z; s[c][w4 + 3] = v.w;
    }
    __syncthreads();

#pragma unroll
    for (int it = 0; it < 4; it++) {
        int w  = it * 16 + (tid >> 4);
        int c4 = (tid & 15) * 4;
        float f0 = s[c4 + 0][w], f1 = s[c4 + 1][w];
        float f2 = s[c4 + 2][w], f3 = s[c4 + 3][w];
        size_t o = ((size_t)b * NW + w0 + w) * NC + c0 + c4;
        *(uint2*)(g_xth + o) = make_uint2(h2(f0, f1), h2(f2, f3));
    }
}

// ---------------- Kernel 1: QKV GEMM (fp16 1-product) -----------------------

__global__ void __launch_bounds__(256, 1)
qkv_mma_kernel(const float* __restrict__ bq, const float* __restrict__ bk,
               const float* __restrict__ bv) {
    extern __shared__ uint16_t smem[];
    const int b  = blockIdx.z;
    const int m0 = blockIdx.y * 128;
    const int w0 = blockIdx.x * 128;
    const int tid  = threadIdx.x;
    const int wid  = tid >> 5;
    const int lane = tid & 31;
    const int wm = wid >> 2, wn = wid & 3;

    const uint32_t sbase = smem_u32(smem);

    const int row = tid >> 1;
    const int c16 = (tid & 1) * 16;
    const uint16_t* rA = g_wh + (size_t)(m0 + row) * NC + c16;
    const uint16_t* rB = g_xth + ((size_t)b * NW + w0 + row) * NC + c16;

    float acc[4][4][4];
#pragma unroll
    for (int mf = 0; mf < 4; mf++)
#pragma unroll
        for (int nf = 0; nf < 4; nf++)
#pragma unroll
            for (int e = 0; e < 4; e++) acc[mf][nf][e] = 0.f;

    uint4 pa[2], pb[2];
#pragma unroll
    for (int q = 0; q < 2; q++) {
        pa[q] = *(const uint4*)(rA + 8 * q);
        pb[q] = *(const uint4*)(rB + 8 * q);
    }

    constexpr int NCH = NC / 32;   // 16
#pragma unroll 1
    for (int chunk = 0; chunk < NCH; chunk++) {
        const int p = chunk & 1;
        uint16_t* sA = smem + p * (ST32 / 2);
        uint16_t* sB = sA + T32 / 2;
#pragma unroll
        for (int q = 0; q < 2; q++) {
            *(uint4*)(sA + row * SR32 + c16 + 8 * q) = pa[q];
            *(uint4*)(sB + row * SR32 + c16 + 8 * q) = pb[q];
        }
        __syncthreads();

        if (chunk < NCH - 1) {
            const int kk = (chunk + 1) * 32;
#pragma unroll
            for (int q = 0; q < 2; q++) {
                pa[q] = *(const uint4*)(rA + kk + 8 * q);
                pb[q] = *(const uint4*)(rB + kk + 8 * q);
            }
        }

        const uint32_t aBase = sbase + p * ST32;
        stage1<SR32, SR32, 2>(acc, aBase, aBase + T32, wm, wn, lane);
    }

#pragma unroll
    for (int mf = 0; mf < 4; mf++) {
#pragma unroll
        for (int half = 0; half < 2; half++) {
            const int m = m0 + wm * 64 + mf * 16 + (lane >> 2) + 8 * half;
            if (m0 == 0 && m < 128) {
                const float bias = (m < NQ) ? bq[m] : bk[m - NQ];
#pragma unroll
                for (int nf = 0; nf < 4; nf++) {
                    const int n = w0 + wn * 32 + nf * 8 + ((lane & 3) << 1);
                    float y0 = acc[mf][nf][2 * half + 0] + bias;
                    float y1 = acc[mf][nf][2 * half + 1] + bias;
                    size_t o0 = ((size_t)b * NW + n) * 128 + m;
                    g_qkh[o0]       = h1(y0);
                    g_qkh[o0 + 128] = h1(y1);
                }
            } else if (m0 > 0) {
                const int c = m - 128;
                const float bias = bv[c];
#pragma unroll
                for (int nf = 0; nf < 4; nf++) {
                    const int n = w0 + wn * 32 + nf * 8 + ((lane & 3) << 1);
                    float y0 = acc[mf][nf][2 * half + 0] + bias;
                    float y1 = acc[mf][nf][2 * half + 1] + bias;
                    *(uint32_t*)(g_vh + ((size_t)b * NC + c) * NW + n) = h2(y0, y1);
                }
            }
        }
    }
}

// ---------------- Kernel 2: pmax — fused energy + softmax -------------------
// Per (b, i-tile): phase 1 computes S tile-by-tile in regs tracking row max;
// phase 2 recomputes S, P = exp(S - m), accumulates row sums, writes fp16 P
// (unnormalized) and g_srow.  S never touches gmem.

__global__ void __launch_bounds__(256, 1)
pmax_kernel() {
    extern __shared__ uint16_t smem[];
    const int b  = blockIdx.y;
    const int i0 = blockIdx.x * 128;
    const int tid  = threadIdx.x;
    const int lane = tid & 31;
    const int wid  = tid >> 5;
    const int wm = wid >> 2, wn = wid & 3;

    const uint32_t sbase = smem_u32(smem);
    uint16_t* sQ = smem;                          // [128][72]
    float* sRed = (float*)(smem + PM_OFF_RED / 2);  // [4][128]
    float* sM   = (float*)(smem + PM_OFF_M / 2);    // [128]
    float* sS   = (float*)(smem + PM_OFF_S / 2);    // [128]
    uint16_t* sP = smem + PM_OFF_P / 2;             // [128][136]

    const int row = tid >> 1;
    const int h32 = (tid & 1) * 32;

    // load Q tile (persistent)
    {
        const uint16_t* qh = g_qkh + ((size_t)b * NW + i0 + row) * 128 + h32;
#pragma unroll
        for (int q = 0; q < 4; q++)
            *(uint4*)(sQ + row * SR64 + h32 + 8 * q) = *(const uint4*)(qh + 8 * q);
    }
    if (tid < 128) { sM[tid] = -1e30f; sS[tid] = 0.f; }
    __syncthreads();

    const uint16_t* kptr = g_qkh + ((size_t)b * NW + row) * 128 + 64 + h32;
    constexpr size_t KSTRIDE = (size_t)128 * 128;   // j-tile advance in elements

    // ---------------- phase 1: row max ----------------
    {
        uint4 pk[4];
#pragma unroll
        for (int q = 0; q < 4; q++) pk[q] = *(const uint4*)(kptr + 8 * q);

#pragma unroll 1
        for (int jt = 0; jt < 16; jt++) {
            uint16_t* sK = smem + (T64 + (jt & 1) * T64) / 2;
#pragma unroll
            for (int q = 0; q < 4; q++)
                *(uint4*)(sK + row * SR64 + h32 + 8 * q) = pk[q];
            __syncthreads();
            if (jt < 15) {
#pragma unroll
                for (int q = 0; q < 4; q++)
                    pk[q] = *(const uint4*)(kptr + (jt + 1) * KSTRIDE + 8 * q);
            }

            float S[4][4][4];
#pragma unroll
            for (int mf = 0; mf < 4; mf++)
#pragma unroll
                for (int nf = 0; nf < 4; nf++)
#pragma unroll
                    for (int e = 0; e < 4; e++) S[mf][nf][e] = 0.f;
            stage1<SR64, SR64, 4>(S, sbase, sbase + T64 + (jt & 1) * T64,
                                  wm, wn, lane);

#pragma unroll
            for (int mf = 0; mf < 4; mf++)
#pragma unroll
                for (int e = 0; e < 2; e++) {
                    const int r = wm * 64 + mf * 16 + (lane >> 2) + 8 * e;
                    float v = S[mf][0][2 * e];
#pragma unroll
                    for (int nf = 0; nf < 4; nf++) {
                        v = fmaxf(v, S[mf][nf][2 * e]);
                        v = fmaxf(v, S[mf][nf][2 * e + 1]);
                    }
                    v = fmaxf(v, __shfl_xor_sync(0xffffffffu, v, 1));
                    v = fmaxf(v, __shfl_xor_sync(0xffffffffu, v, 2));
                    if ((lane & 3) == 0) sRed[wn * 128 + r] = v;
                }
            __syncthreads();
            if (tid < 128) {
                float m = fmaxf(fmaxf(sRed[tid], sRed[128 + tid]),
                                fmaxf(sRed[256 + tid], sRed[384 + tid]));
                sM[tid] = fmaxf(sM[tid], m);
            }
            __syncthreads();
        }
    }

    // ---------------- phase 2: P = exp(S - m), sums, store ----------------
    {
        uint4 pk[4];
#pragma unroll
        for (int q = 0; q < 4; q++) pk[q] = *(const uint4*)(kptr + 8 * q);

#pragma unroll 1
        for (int jt = 0; jt < 16; jt++) {
            uint16_t* sK = smem + (T64 + (jt & 1) * T64) / 2;
#pragma unroll
            for (int q = 0; q < 4; q++)
                *(uint4*)(sK + row * SR64 + h32 + 8 * q) = pk[q];
            __syncthreads();
            if (jt < 15) {
#pragma unroll
                for (int q = 0; q < 4; q++)
                    pk[q] = *(const uint4*)(kptr + (jt + 1) * KSTRIDE + 8 * q);
            }

            float S[4][4][4];
#pragma unroll
            for (int mf = 0; mf < 4; mf++)
#pragma unroll
                for (int nf = 0; nf < 4; nf++)
#pragma unroll
                    for (int e = 0; e < 4; e++) S[mf][nf][e] = 0.f;
            stage1<SR64, SR64, 4>(S, sbase, sbase + T64 + (jt & 1) * T64,
                                  wm, wn, lane);

#pragma unroll
            for (int mf = 0; mf < 4; mf++)
#pragma unroll
                for (int e = 0; e < 2; e++) {
                    const int r = wm * 64 + mf * 16 + (lane >> 2) + 8 * e;
                    const float mr = sM[r];
                    float ssum = 0.f;
#pragma unroll
                    for (int nf = 0; nf < 4; nf++) {
                        float p0 = __expf(S[mf][nf][2 * e + 0] - mr);
                        float p1 = __expf(S[mf][nf][2 * e + 1] - mr);
                        ssum += p0 + p1;
                        const int col = wn * 32 + nf * 8 + ((lane & 3) << 1);
                        *(uint32_t*)(sP + r * SRP + col) = h2(p0, p1);
                    }
                    ssum += __shfl_xor_sync(0xffffffffu, ssum, 1);
                    ssum += __shfl_xor_sync(0xffffffffu, ssum, 2);
                    if ((lane & 3) == 0) sRed[wn * 128 + r] = ssum;
                }
            __syncthreads();
            if (tid < 128)
                sS[tid] += sRed[tid] + sRed[128 + tid] +
                           sRed[256 + tid] + sRed[384 + tid];
            // coalesced P store
            {
                const int r2 = tid >> 1;
                const int hh = (tid & 1) * 64;
                uint16_t* dst = g_ph + ((size_t)b * NW + i0 + r2) * NW + jt * 128 + hh;
#pragma unroll
                for (int q = 0; q < 8; q++)
                    *(uint4*)(dst + 8 * q) = *(uint4*)(sP + r2 * SRP + hh + 8 * q);
            }
            __syncthreads();
        }
    }

    if (tid < 128) g_srow[(size_t)b * NW + i0 + tid] = sS[tid];
}

// ---------------- Kernel 4: out GEMM (fp16 1-product, /s in epilogue) -------
// out[c,i] = gamma/s[i] * sum_j v[c,j] P[i,j] + x[c,i].

__global__ void __launch_bounds__(256, 1)
out_mma_kernel(const float* __restrict__ x, const float* __restrict__ gamma,
               float* __restrict__ out) {
    extern __shared__ uint16_t smem[];
    const int b  = blockIdx.z;
    const int c0 = blockIdx.x * 128;
    const int i0 = blockIdx.y * 128;
    const int tid  = threadIdx.x;
    const int wid  = tid >> 5;
    const int lane = tid & 31;
    const int wm = wid >> 2, wn = wid & 3;

    const uint32_t sbase = smem_u32(smem);

    const int row = tid >> 1;
    const int c16 = (tid & 1) * 16;
    const uint16_t* rA = g_vh + ((size_t)b * NC + c0 + row) * NW + c16;
    const uint16_t* rB = g_ph + ((size_t)b * NW + i0 + row) * NW + c16;

    float acc[4][4][4];
#pragma unroll
    for (int mf = 0; mf < 4; mf++)
#pragma unroll
        for (int nf = 0; nf < 4; nf++)
#pragma unroll
            for (int e = 0; e < 4; e++) acc[mf][nf][e] = 0.f;

    uint4 pa[2], pb[2];
#pragma unroll
    for (int q = 0; q < 2; q++) {
        pa[q] = *(const uint4*)(rA + 8 * q);
        pb[q] = *(const uint4*)(rB + 8 * q);
    }

    constexpr int NCH = NW / 32;   // 64
#pragma unroll 1
    for (int chunk = 0; chunk < NCH; chunk++) {
        const int p = chunk & 1;
        uint16_t* sA = smem + p * (ST32 / 2);
        uint16_t* sB = sA + T32 / 2;
#pragma unroll
        for (int q = 0; q < 2; q++) {
            *(uint4*)(sA + row * SR32 + c16 + 8 * q) = pa[q];
            *(uint4*)(sB + row * SR32 + c16 + 8 * q) = pb[q];
        }
        __syncthreads();

        if (chunk < NCH - 1) {
            const int kk = (chunk + 1) * 32;
#pragma unroll
            for (int q = 0; q < 2; q++) {
                pa[q] = *(const uint4*)(rA + kk + 8 * q);
                pb[q] = *(const uint4*)(rB + kk + 8 * q);
            }
        }

        const uint32_t aBase = sbase + p * ST32;
        stage1<SR32, SR32, 2>(acc, aBase, aBase + T32, wm, wn, lane);
    }

    const float gam = gamma[0];
    // per-nf inverse row sums (n depends only on nf, not mf)
    float iv0[4], iv1[4];
#pragma unroll
    for (int nf = 0; nf < 4; nf++) {
        const int n = i0 + wn * 32 + nf * 8 + ((lane & 3) << 1);
        float2 sv = *(const float2*)(g_srow + (size_t)b * NW + n);
        iv0[nf] = gam / sv.x;
        iv1[nf] = gam / sv.y;
    }
#pragma unroll
    for (int mf = 0; mf < 4; mf++) {
        const int m = c0 + wm * 64 + mf * 16 + (lane >> 2);
#pragma unroll
        for (int nf = 0; nf < 4; nf++) {
            const int n = i0 + wn * 32 + nf * 8 + ((lane & 3) << 1);
            size_t o0 = ((size_t)b * NC + m) * NW + n;
            float2 xv0 = *(const float2*)(x + o0);
            *(float2*)(out + o0) =
                make_float2(fmaf(acc[mf][nf][0], iv0[nf], xv0.x),
                            fmaf(acc[mf][nf][1], iv1[nf], xv0.y));
            size_t o1 = o0 + (size_t)8 * NW;
            float2 xv1 = *(const float2*)(x + o1);
            *(float2*)(out + o1) =
                make_float2(fmaf(acc[mf][nf][2], iv0[nf], xv1.x),
                            fmaf(acc[mf][nf][3], iv1[nf], xv1.y));
        }
    }
}

// ---------------- launch ----------------------------------------------------

extern "C" void kernel_launch(void* const* d_in, const int* in_sizes, int n_in,
                              void* d_out, int out_size) {
    const float* x     = (const float*)d_in[0];
    const float* Wq    = (const float*)d_in[1];
    const float* bq    = (const float*)d_in[2];
    const float* Wk    = (const float*)d_in[3];
    const float* bk    = (const float*)d_in[4];
    const float* Wv    = (const float*)d_in[5];
    const float* bv    = (const float*)d_in[6];
    const float* gamma = (const float*)d_in[7];
    float* out = (float*)d_out;

    cudaFuncSetAttribute(qkv_mma_kernel,
                         cudaFuncAttributeMaxDynamicSharedMemorySize, GEMM_SMEM);
    cudaFuncSetAttribute(pmax_kernel,
                         cudaFuncAttributeMaxDynamicSharedMemorySize, PM_SMEM);
    cudaFuncSetAttribute(out_mma_kernel,
                         cudaFuncAttributeMaxDynamicSharedMemorySize, GEMM_SMEM);

    wprep_kernel<<<NM, 128>>>(Wq, Wk, Wv);
    transpose_x_kernel<<<dim3(NW / 64, NC / 64, NB), 256>>>(x);
    qkv_mma_kernel<<<dim3(NW / 128, 5, NB), 256, GEMM_SMEM>>>(bq, bk, bv);
    pmax_kernel<<<dim3(NW / 128, NB), 256, PM_SMEM>>>();
    out_mma_kernel<<<dim3(NC / 128, NW / 128, NB), 256, GEMM_SMEM>>>(x, gamma, out);
}